// round 3
// baseline (speedup 1.0000x reference)
#include <cuda_runtime.h>
#include <cuda.h>
#include <cuda_bf16.h>
#include <cstdint>

// ============================================================================
// Problem dims
// ============================================================================
#define NDIM 4096
#define KDIM 4096
#define ODIM 4096

// GEMM tiling (int8 path)
#define BM 128
#define BN 128
#define BK 128                     // int8 elems per K-chunk (128 B rows, SW128)
#define STAGES 4
#define KCHUNKS (KDIM / BK)        // 32

// SMEM layout (dynamic):
//  [0:32)   full barriers (4 x 8B)
//  [1024 + s*49152) stage s: A_hi (16KB) | A_lo (16KB) | B (16KB)
#define SMEM_DATA   1024
#define STAGE_BYTES 49152
#define OFF_ALO     16384
#define OFF_B       32768
#define SMEM_TOTAL  (SMEM_DATA + STAGES * STAGE_BYTES)   // 197632

// ============================================================================
// Scratch (device globals; no allocation allowed)
// ============================================================================
static __device__ __align__(1024) int8_t g_Xhi[(size_t)NDIM * KDIM];  // 16MB
static __device__ __align__(1024) int8_t g_Xlo[(size_t)NDIM * KDIM];  // 16MB
static __device__ __align__(1024) int8_t g_Wq [(size_t)ODIM * KDIM];  // 16MB
static __device__ float g_srow[NDIM];

// ============================================================================
// PTX helpers (base sm_103: TMA + mbarrier + ldmatrix + mma.sync)
// ============================================================================
__device__ __forceinline__ uint32_t smem_u32(const void* p) {
    uint32_t a;
    asm("{ .reg .u64 t; cvta.to.shared.u64 t, %1; cvt.u32.u64 %0, t; }" : "=r"(a) : "l"(p));
    return a;
}

#define MBARRIER_INIT(addr, cnt) \
    asm volatile("mbarrier.init.shared.b64 [%0], %1;" :: "r"((uint32_t)(addr)), "r"((uint32_t)(cnt)) : "memory")

#define MBARRIER_EXPECT_TX(addr, bytes) \
    asm volatile("mbarrier.arrive.expect_tx.shared.b64 _, [%0], %1;" :: "r"((uint32_t)(addr)), "r"((uint32_t)(bytes)) : "memory")

#define MBARRIER_WAIT_PARITY(mbar_smem_addr, phase_parity) do {                                   \
    uint32_t _mbar = (uint32_t)(mbar_smem_addr);                                                  \
    uint32_t _parity = (uint32_t)(phase_parity);                                                  \
    uint32_t _done;                                                                               \
    asm volatile("{\n\t.reg .pred p;\n\t"                                                         \
        "mbarrier.try_wait.parity.acquire.cta.shared::cta.b64 p, [%1], %2;\n\t"                   \
        "selp.b32 %0, 1, 0, p;\n\t}"                                                              \
        : "=r"(_done) : "r"(_mbar), "r"(_parity) : "memory");                                     \
    if (!_done) {                                                                                 \
        asm volatile("{\n\t.reg .pred P1;\n\t"                                                    \
            "WAIT_LOOP_%=:\n\t"                                                                   \
            "mbarrier.try_wait.parity.acquire.cta.shared::cta.b64 P1, [%0], %1, 0x989680;\n\t"    \
            "@P1 bra.uni WAIT_DONE_%=;\n\t"                                                       \
            "bra.uni WAIT_LOOP_%=;\n\t"                                                           \
            "WAIT_DONE_%=:\n\t}"                                                                  \
            :: "r"(_mbar), "r"(_parity) : "memory");                                              \
    }                                                                                             \
} while (0)

__device__ __forceinline__ void tma2d(uint32_t smem_addr, const CUtensorMap* tm,
                                      int cx, int cy, uint32_t mbar) {
    asm volatile(
        "cp.async.bulk.tensor.2d.shared::cta.global.tile.mbarrier::complete_tx::bytes "
        "[%0], [%1, {%2, %3}], [%4];"
        :: "r"(smem_addr), "l"(tm), "r"(cx), "r"(cy), "r"(mbar) : "memory");
}

__device__ __forceinline__ void ldsm4(uint32_t& r0, uint32_t& r1, uint32_t& r2, uint32_t& r3,
                                      uint32_t addr) {
    asm volatile("ldmatrix.sync.aligned.m8n8.x4.shared.b16 {%0,%1,%2,%3}, [%4];"
                 : "=r"(r0), "=r"(r1), "=r"(r2), "=r"(r3) : "r"(addr));
}

// s8 x s8 -> s32, m16n8k32
__device__ __forceinline__ void mma_s8(int* c, const uint32_t* a, const uint32_t* b) {
    asm volatile(
        "mma.sync.aligned.m16n8k32.row.col.s32.s8.s8.s32 "
        "{%0,%1,%2,%3}, {%4,%5,%6,%7}, {%8,%9}, {%0,%1,%2,%3};"
        : "+r"(c[0]), "+r"(c[1]), "+r"(c[2]), "+r"(c[3])
        : "r"(a[0]), "r"(a[1]), "r"(a[2]), "r"(a[3]), "r"(b[0]), "r"(b[1]));
}

// ============================================================================
// Kernel 1: per-row two-level int8 quantization of X.
//   x = s_row * (q_hi + q_lo/128),  |err| <= s_row/256
// One block (128 threads) per row.
// ============================================================================
__global__ void __launch_bounds__(128) k_quant_x(const float4* __restrict__ x,
                                                 uint32_t* __restrict__ hi,
                                                 uint32_t* __restrict__ lo,
                                                 float* __restrict__ srow) {
    __shared__ float warpmax[4];
    int row = blockIdx.x;
    int tid = threadIdx.x;
    const float4* xr = x + (size_t)row * (KDIM / 4);

    float4 v[8];
    float m = 0.0f;
    #pragma unroll
    for (int j = 0; j < 8; j++) {
        v[j] = xr[tid + j * 128];
        m = fmaxf(m, fmaxf(fmaxf(fabsf(v[j].x), fabsf(v[j].y)),
                           fmaxf(fabsf(v[j].z), fabsf(v[j].w))));
    }
    #pragma unroll
    for (int o = 16; o > 0; o >>= 1)
        m = fmaxf(m, __shfl_xor_sync(0xFFFFFFFFu, m, o));
    if ((tid & 31) == 0) warpmax[tid >> 5] = m;
    __syncthreads();
    m = fmaxf(fmaxf(warpmax[0], warpmax[1]), fmaxf(warpmax[2], warpmax[3]));

    float s = m * (1.0f / 127.0f);
    float inv = (m > 0.0f) ? (127.0f / m) : 0.0f;
    float inv128 = inv * 128.0f;
    if (tid == 0) srow[row] = s;

    uint32_t* hr = hi + (size_t)row * (KDIM / 4);
    uint32_t* lr = lo + (size_t)row * (KDIM / 4);
    #pragma unroll
    for (int j = 0; j < 8; j++) {
        int h0 = __float2int_rn(v[j].x * inv);
        int h1 = __float2int_rn(v[j].y * inv);
        int h2 = __float2int_rn(v[j].z * inv);
        int h3 = __float2int_rn(v[j].w * inv);
        int l0 = __float2int_rn((v[j].x - (float)h0 * s) * inv128);
        int l1 = __float2int_rn((v[j].y - (float)h1 * s) * inv128);
        int l2 = __float2int_rn((v[j].z - (float)h2 * s) * inv128);
        int l3 = __float2int_rn((v[j].w - (float)h3 * s) * inv128);
        uint32_t H = (h0 & 0xFF) | ((h1 & 0xFF) << 8) | ((h2 & 0xFF) << 16) | ((h3 & 0xFF) << 24);
        uint32_t L = (l0 & 0xFF) | ((l1 & 0xFF) << 8) | ((l2 & 0xFF) << 16) | ((l3 & 0xFF) << 24);
        hr[tid + j * 128] = H;
        lr[tid + j * 128] = L;
    }
}

// ============================================================================
// Kernel 2: unpack int4 weights -> centered int8 (q - 8), exact
// ============================================================================
__device__ __forceinline__ uint32_t unpack4b(int a, int b) {
    int x0 = (a & 0xF) - 8, x1 = ((a >> 4) & 0xF) - 8;
    int x2 = (b & 0xF) - 8, x3 = ((b >> 4) & 0xF) - 8;
    return (x0 & 0xFF) | ((x1 & 0xFF) << 8) | ((x2 & 0xFF) << 16) | ((x3 & 0xFF) << 24);
}

__global__ void __launch_bounds__(256) k_cvt_w(const int4* __restrict__ wp,
                                               uint2* __restrict__ wq, int n4) {
    int i = blockIdx.x * blockDim.x + threadIdx.x;
    if (i >= n4) return;
    int4 p = wp[i];
    uint2 o;
    o.x = unpack4b(p.x, p.y);
    o.y = unpack4b(p.z, p.w);
    wq[i] = o;
}

// ============================================================================
// Kernel 3: int8 IMMA GEMM, TMA 4-stage pipeline.
// CTA 128x128, 256 threads, warp grid 4(m) x 2(n), warp tile 32x64.
// Two persistent int32 accumulators (hi / lo); exact integer accumulation.
// ============================================================================
__global__ void __launch_bounds__(256, 1) gemm_kernel(
    const __grid_constant__ CUtensorMap tmA_hi,
    const __grid_constant__ CUtensorMap tmA_lo,
    const __grid_constant__ CUtensorMap tmB,
    const float* __restrict__ srow,
    const float* __restrict__ scales,
    const float* __restrict__ bias,
    float* __restrict__ out)
{
    extern __shared__ char smem[];
    uint32_t sb = smem_u32(smem);
    int tid = threadIdx.x, wid = tid >> 5, lane = tid & 31;
    int warp_m = wid & 3;          // 0..3 -> 32-row slice
    int warp_n = wid >> 2;         // 0..1 -> 64-col slice

    // Block-swizzled tile mapping (8 row-tiles per group -> wave fits L2)
    const int colTiles = ODIM / BN;        // 32
    const int GROUP = 8;
    int g = blockIdx.x / (GROUP * colTiles);
    int r = blockIdx.x % (GROUP * colTiles);
    int rt = g * GROUP + (r % GROUP);
    int ct = r / GROUP;
    int rowBase = rt * BM;
    int colBase = ct * BN;

    if (tid == 0) {
        #pragma unroll
        for (int s = 0; s < STAGES; s++) MBARRIER_INIT(sb + 8 * s, 1);
    }
    __syncthreads();

    // Prologue: prefetch chunks 0..STAGES-1
    if (tid == 0) {
        #pragma unroll
        for (int p = 0; p < STAGES; p++) {
            uint32_t fb = sb + 8 * p;
            MBARRIER_EXPECT_TX(fb, (uint32_t)STAGE_BYTES);
            uint32_t st = sb + SMEM_DATA + p * STAGE_BYTES;
            tma2d(st,           &tmA_hi, p * BK, rowBase, fb);
            tma2d(st + OFF_ALO, &tmA_lo, p * BK, rowBase, fb);
            tma2d(st + OFF_B,   &tmB,    p * BK, colBase, fb);
        }
    }

    // ldmatrix addressing: 128 B rows, SW128 swizzle = col ^ ((row&7)<<4)
    uint32_t rowA = (uint32_t)(warp_m * 32 + (lane & 15));
    uint32_t rowB = (uint32_t)(warp_n * 64 + (lane & 15));
    uint32_t ksel = (uint32_t)((lane >> 4) << 4);   // 0 or 16 bytes
    uint32_t aRel0 = rowA * 128;
    uint32_t bRel0 = rowB * 128;
    uint32_t xorA = (rowA & 7) << 4;
    uint32_t xorB = (rowB & 7) << 4;

    int accH[2][8][4], accL[2][8][4];
    #pragma unroll
    for (int i = 0; i < 2; i++)
        #pragma unroll
        for (int j = 0; j < 8; j++)
            #pragma unroll
            for (int k = 0; k < 4; k++) { accH[i][j][k] = 0; accL[i][j][k] = 0; }

    #pragma unroll 1
    for (int i = 0; i < KCHUNKS; i++) {
        int s = i % STAGES;
        MBARRIER_WAIT_PARITY(sb + 8 * s, (i / STAGES) & 1);
        uint32_t sAhi = sb + SMEM_DATA + s * STAGE_BYTES;
        uint32_t sAlo = sAhi + OFF_ALO;
        uint32_t sB   = sAhi + OFF_B;

        #pragma unroll
        for (int ks = 0; ks < 4; ks++) {          // k32 steps within 128-byte chunk
            uint32_t kb = (uint32_t)(ks * 32) + ksel;
            uint32_t kbA = kb ^ xorA;
            uint32_t kbB = kb ^ xorB;

            // B fragments: 4x ldsm.x4 covering n64 x k32 (shared by both passes)
            uint32_t bf[8][2];
            #pragma unroll
            for (int t = 0; t < 4; t++)
                ldsm4(bf[2 * t][0], bf[2 * t + 1][0], bf[2 * t][1], bf[2 * t + 1][1],
                      sB + bRel0 + (uint32_t)(t * 16 * 128) + kbB);

            uint32_t af[2][4];
            // hi pass
            #pragma unroll
            for (int mt = 0; mt < 2; mt++)
                ldsm4(af[mt][0], af[mt][1], af[mt][2], af[mt][3],
                      sAhi + aRel0 + (uint32_t)(mt * 16 * 128) + kbA);
            #pragma unroll
            for (int mt = 0; mt < 2; mt++)
                #pragma unroll
                for (int nt = 0; nt < 8; nt++)
                    mma_s8(accH[mt][nt], af[mt], bf[nt]);

            // lo pass (reuses B fragments)
            #pragma unroll
            for (int mt = 0; mt < 2; mt++)
                ldsm4(af[mt][0], af[mt][1], af[mt][2], af[mt][3],
                      sAlo + aRel0 + (uint32_t)(mt * 16 * 128) + kbA);
            #pragma unroll
            for (int mt = 0; mt < 2; mt++)
                #pragma unroll
                for (int nt = 0; nt < 8; nt++)
                    mma_s8(accL[mt][nt], af[mt], bf[nt]);
        }

        __syncthreads();
        int pc = i + STAGES;
        if (tid == 0 && pc < KCHUNKS) {
            uint32_t fb = sb + 8 * s;
            MBARRIER_EXPECT_TX(fb, (uint32_t)STAGE_BYTES);
            uint32_t st = sb + SMEM_DATA + s * STAGE_BYTES;
            tma2d(st,           &tmA_hi, pc * BK, rowBase, fb);
            tma2d(st + OFF_ALO, &tmA_lo, pc * BK, rowBase, fb);
            tma2d(st + OFF_B,   &tmB,    pc * BK, colBase, fb);
        }
    }

    // Epilogue: y = s_row * (hi + lo/128) * scale_col + bias_col
    const float INV128 = 1.0f / 128.0f;
    int row0 = rowBase + warp_m * 32 + (lane >> 2);
    int col0 = colBase + warp_n * 64 + (lane & 3) * 2;
    float sr[2][2];
    sr[0][0] = __ldg(srow + row0);
    sr[0][1] = __ldg(srow + row0 + 8);
    sr[1][0] = __ldg(srow + row0 + 16);
    sr[1][1] = __ldg(srow + row0 + 24);
    #pragma unroll
    for (int nt = 0; nt < 8; nt++) {
        int c = col0 + nt * 8;
        float s0 = __ldg(scales + c), s1 = __ldg(scales + c + 1);
        float b0 = __ldg(bias + c),   b1 = __ldg(bias + c + 1);
        #pragma unroll
        for (int mt = 0; mt < 2; mt++) {
            int rr = row0 + mt * 16;
            float v00 = fmaf((float)accH[mt][nt][0] + (float)accL[mt][nt][0] * INV128, sr[mt][0] * s0, b0);
            float v01 = fmaf((float)accH[mt][nt][1] + (float)accL[mt][nt][1] * INV128, sr[mt][0] * s1, b1);
            float v10 = fmaf((float)accH[mt][nt][2] + (float)accL[mt][nt][2] * INV128, sr[mt][1] * s0, b0);
            float v11 = fmaf((float)accH[mt][nt][3] + (float)accL[mt][nt][3] * INV128, sr[mt][1] * s1, b1);
            *reinterpret_cast<float2*>(out + (size_t)rr * ODIM + c) = make_float2(v00, v01);
            *reinterpret_cast<float2*>(out + (size_t)(rr + 8) * ODIM + c) = make_float2(v10, v11);
        }
    }
}

// ============================================================================
// Host side
// ============================================================================
typedef CUresult (*PFN_encodeTiled)(
    CUtensorMap*, CUtensorMapDataType, cuuint32_t, void*,
    const cuuint64_t*, const cuuint64_t*, const cuuint32_t*, const cuuint32_t*,
    CUtensorMapInterleave, CUtensorMapSwizzle, CUtensorMapL2promotion, CUtensorMapFloatOOBfill);

static PFN_encodeTiled get_encoder() {
    void* fn = nullptr;
    cudaDriverEntryPointQueryResult qr;
    cudaGetDriverEntryPointByVersion("cuTensorMapEncodeTiled", &fn, 12000,
                                     cudaEnableDefault, &qr);
    return (PFN_encodeTiled)fn;
}

static void encode_u8_2d(PFN_encodeTiled enc, CUtensorMap* tm, void* base,
                         uint64_t d0, uint64_t d1, uint32_t b0, uint32_t b1) {
    cuuint64_t gd[2] = {d0, d1};
    cuuint64_t gs[1] = {d0};       // row stride, bytes
    cuuint32_t box[2] = {b0, b1};
    cuuint32_t es[2] = {1, 1};
    enc(tm, CU_TENSOR_MAP_DATA_TYPE_UINT8, 2, base, gd, gs, box, es,
        CU_TENSOR_MAP_INTERLEAVE_NONE, CU_TENSOR_MAP_SWIZZLE_128B,
        CU_TENSOR_MAP_L2_PROMOTION_L2_128B, CU_TENSOR_MAP_FLOAT_OOB_FILL_NONE);
}

extern "C" void kernel_launch(void* const* d_in, const int* in_sizes, int n_in,
                              void* d_out, int out_size) {
    const float* x  = (const float*)d_in[0];
    const int*   wp = (const int*)d_in[1];
    const float* ws = (const float*)d_in[2];
    const float* bs = (const float*)d_in[3];
    float* out = (float*)d_out;

    void *pXhi, *pXlo, *pWq, *pSrow;
    cudaGetSymbolAddress(&pXhi, g_Xhi);
    cudaGetSymbolAddress(&pXlo, g_Xlo);
    cudaGetSymbolAddress(&pWq,  g_Wq);
    cudaGetSymbolAddress(&pSrow, g_srow);

    // 1) precompute: quantize X (two-level int8), unpack W to centered int8
    k_quant_x<<<NDIM, 128>>>((const float4*)x, (uint32_t*)pXhi, (uint32_t*)pXlo,
                             (float*)pSrow);
    {
        int n4 = (ODIM * (KDIM / 2)) / 4;
        k_cvt_w<<<(n4 + 255) / 256, 256>>>((const int4*)wp, (uint2*)pWq, n4);
    }

    // 2) TMA descriptors
    PFN_encodeTiled enc = get_encoder();
    CUtensorMap tA_hi, tA_lo, tB;
    encode_u8_2d(enc, &tA_hi, pXhi, KDIM, NDIM, BK, BM);
    encode_u8_2d(enc, &tA_lo, pXlo, KDIM, NDIM, BK, BM);
    encode_u8_2d(enc, &tB,    pWq,  KDIM, ODIM, BK, BN);

    // 3) GEMM
    cudaFuncSetAttribute(gemm_kernel, cudaFuncAttributeMaxDynamicSharedMemorySize, SMEM_TOTAL);
    int grid = (NDIM / BM) * (ODIM / BN);   // 1024
    gemm_kernel<<<grid, 256, SMEM_TOTAL>>>(tA_hi, tA_lo, tB,
                                           (const float*)pSrow, ws, bs, out);
}

// round 4
// speedup vs baseline: 4.7278x; 4.7278x over previous
#include <cuda_runtime.h>
#include <cuda.h>
#include <cuda_fp16.h>
#include <cstdint>

// ============================================================================
// Problem dims
// ============================================================================
#define NDIM 4096
#define KDIM 4096
#define ODIM 4096

// GEMM tiling (fp16 single-pass)
#define BM 128
#define BN 128
#define BK 64                      // fp16 elems per K-chunk (128 B rows, SW128)
#define STAGES 5
#define KCHUNKS (KDIM / BK)        // 64

// SMEM layout (dynamic):
//  [0:40)   full barriers (5 x 8B)
//  [1024 + s*32768) stage s: A (16KB) | B (16KB)
#define SMEM_DATA   1024
#define STAGE_BYTES 32768
#define OFF_B       16384
#define SMEM_TOTAL  (SMEM_DATA + STAGES * STAGE_BYTES)   // 164864

// ============================================================================
// Scratch (device globals; no allocation allowed)
// ============================================================================
static __device__ __align__(1024) __half g_Xh[(size_t)NDIM * KDIM];  // 32MB
static __device__ __align__(1024) __half g_Wq[(size_t)ODIM * KDIM];  // 32MB

// ============================================================================
// PTX helpers (base sm_103: TMA + mbarrier + ldmatrix + mma.sync)
// ============================================================================
__device__ __forceinline__ uint32_t smem_u32(const void* p) {
    uint32_t a;
    asm("{ .reg .u64 t; cvta.to.shared.u64 t, %1; cvt.u32.u64 %0, t; }" : "=r"(a) : "l"(p));
    return a;
}

#define MBARRIER_INIT(addr, cnt) \
    asm volatile("mbarrier.init.shared.b64 [%0], %1;" :: "r"((uint32_t)(addr)), "r"((uint32_t)(cnt)) : "memory")

#define MBARRIER_EXPECT_TX(addr, bytes) \
    asm volatile("mbarrier.arrive.expect_tx.shared.b64 _, [%0], %1;" :: "r"((uint32_t)(addr)), "r"((uint32_t)(bytes)) : "memory")

#define MBARRIER_WAIT_PARITY(mbar_smem_addr, phase_parity) do {                                   \
    uint32_t _mbar = (uint32_t)(mbar_smem_addr);                                                  \
    uint32_t _parity = (uint32_t)(phase_parity);                                                  \
    uint32_t _done;                                                                               \
    asm volatile("{\n\t.reg .pred p;\n\t"                                                         \
        "mbarrier.try_wait.parity.acquire.cta.shared::cta.b64 p, [%1], %2;\n\t"                   \
        "selp.b32 %0, 1, 0, p;\n\t}"                                                              \
        : "=r"(_done) : "r"(_mbar), "r"(_parity) : "memory");                                     \
    if (!_done) {                                                                                 \
        asm volatile("{\n\t.reg .pred P1;\n\t"                                                    \
            "WAIT_LOOP_%=:\n\t"                                                                   \
            "mbarrier.try_wait.parity.acquire.cta.shared::cta.b64 P1, [%0], %1, 0x989680;\n\t"    \
            "@P1 bra.uni WAIT_DONE_%=;\n\t"                                                       \
            "bra.uni WAIT_LOOP_%=;\n\t"                                                           \
            "WAIT_DONE_%=:\n\t}"                                                                  \
            :: "r"(_mbar), "r"(_parity) : "memory");                                              \
    }                                                                                             \
} while (0)

__device__ __forceinline__ void tma2d(uint32_t smem_addr, const CUtensorMap* tm,
                                      int cx, int cy, uint32_t mbar) {
    asm volatile(
        "cp.async.bulk.tensor.2d.shared::cta.global.tile.mbarrier::complete_tx::bytes "
        "[%0], [%1, {%2, %3}], [%4];"
        :: "r"(smem_addr), "l"(tm), "r"(cx), "r"(cy), "r"(mbar) : "memory");
}

__device__ __forceinline__ void ldsm4(uint32_t& r0, uint32_t& r1, uint32_t& r2, uint32_t& r3,
                                      uint32_t addr) {
    asm volatile("ldmatrix.sync.aligned.m8n8.x4.shared.b16 {%0,%1,%2,%3}, [%4];"
                 : "=r"(r0), "=r"(r1), "=r"(r2), "=r"(r3) : "r"(addr));
}

__device__ __forceinline__ void mma_f16(float* c, const uint32_t* a, const uint32_t* b) {
    asm volatile(
        "mma.sync.aligned.m16n8k16.row.col.f32.f16.f16.f32 "
        "{%0,%1,%2,%3}, {%4,%5,%6,%7}, {%8,%9}, {%0,%1,%2,%3};"
        : "+f"(c[0]), "+f"(c[1]), "+f"(c[2]), "+f"(c[3])
        : "r"(a[0]), "r"(a[1]), "r"(a[2]), "r"(a[3]), "r"(b[0]), "r"(b[1]));
}

// ============================================================================
// Kernel 1: X (fp32) -> fp16 (single rounding; rel err <= 2^-11)
// ============================================================================
__global__ void __launch_bounds__(256) k_cvt_x(const float4* __restrict__ x,
                                               uint2* __restrict__ xh, int n4) {
    int i = blockIdx.x * blockDim.x + threadIdx.x;
    if (i >= n4) return;
    float4 v = x[i];
    __half2 h01 = __floats2half2_rn(v.x, v.y);
    __half2 h23 = __floats2half2_rn(v.z, v.w);
    uint2 H;
    H.x = *reinterpret_cast<uint32_t*>(&h01);
    H.y = *reinterpret_cast<uint32_t*>(&h23);
    xh[i] = H;
}

// ============================================================================
// Kernel 2: unpack int4 weights -> centered fp16 (q - 8), exact
// ============================================================================
__device__ __forceinline__ uint32_t unpack2h(int b) {
    int qlo = (b & 0xF) - 8;
    int qhi = ((b >> 4) & 0xF) - 8;
    __half2 h = __floats2half2_rn((float)qlo, (float)qhi);
    return *reinterpret_cast<uint32_t*>(&h);
}

__global__ void __launch_bounds__(256) k_cvt_w(const int4* __restrict__ wp,
                                               uint4* __restrict__ wq, int n4) {
    int i = blockIdx.x * blockDim.x + threadIdx.x;
    if (i >= n4) return;
    int4 p = wp[i];
    uint4 o;
    o.x = unpack2h(p.x);
    o.y = unpack2h(p.y);
    o.z = unpack2h(p.z);
    o.w = unpack2h(p.w);
    wq[i] = o;
}

// ============================================================================
// Kernel 3: fp16 mma.sync GEMM, TMA 5-stage pipeline.
// CTA 128x128, 256 threads, warp grid 4(m) x 2(n), warp tile 32x64.
// ============================================================================
__global__ void __launch_bounds__(256, 1) gemm_kernel(
    const __grid_constant__ CUtensorMap tmA,
    const __grid_constant__ CUtensorMap tmB,
    const float* __restrict__ scales,
    const float* __restrict__ bias,
    float* __restrict__ out)
{
    extern __shared__ char smem[];
    uint32_t sb = smem_u32(smem);
    int tid = threadIdx.x, wid = tid >> 5, lane = tid & 31;
    int warp_m = wid & 3;          // 0..3 -> 32-row slice
    int warp_n = wid >> 2;         // 0..1 -> 64-col slice

    // Block-swizzled tile mapping (8 row-tiles per group -> wave fits L2)
    const int colTiles = ODIM / BN;        // 32
    const int GROUP = 8;
    int g = blockIdx.x / (GROUP * colTiles);
    int r = blockIdx.x % (GROUP * colTiles);
    int rt = g * GROUP + (r % GROUP);
    int ct = r / GROUP;
    int rowBase = rt * BM;
    int colBase = ct * BN;

    if (tid == 0) {
        #pragma unroll
        for (int s = 0; s < STAGES; s++) MBARRIER_INIT(sb + 8 * s, 1);
    }
    __syncthreads();

    // Prologue: prefetch chunks 0..STAGES-1
    if (tid == 0) {
        #pragma unroll
        for (int p = 0; p < STAGES; p++) {
            uint32_t fb = sb + 8 * p;
            MBARRIER_EXPECT_TX(fb, (uint32_t)STAGE_BYTES);
            uint32_t st = sb + SMEM_DATA + p * STAGE_BYTES;
            tma2d(st,         &tmA, p * BK, rowBase, fb);
            tma2d(st + OFF_B, &tmB, p * BK, colBase, fb);
        }
    }

    // ldmatrix addressing: 128 B rows, SW128 swizzle = col ^ ((row&7)<<4)
    uint32_t rowA = (uint32_t)(warp_m * 32 + (lane & 15));
    uint32_t rowB = (uint32_t)(warp_n * 64 + (lane & 15));
    uint32_t ksel = (uint32_t)((lane >> 4) << 4);   // 0 or 16 bytes
    uint32_t aRel0 = rowA * 128;
    uint32_t bRel0 = rowB * 128;
    uint32_t xorA = (rowA & 7) << 4;
    uint32_t xorB = (rowB & 7) << 4;

    float acc[2][8][4];
    #pragma unroll
    for (int i = 0; i < 2; i++)
        #pragma unroll
        for (int j = 0; j < 8; j++)
            #pragma unroll
            for (int k = 0; k < 4; k++) acc[i][j][k] = 0.0f;

    #pragma unroll 1
    for (int i = 0; i < KCHUNKS; i++) {
        int s = i % STAGES;
        MBARRIER_WAIT_PARITY(sb + 8 * s, (i / STAGES) & 1);
        uint32_t sA = sb + SMEM_DATA + s * STAGE_BYTES;
        uint32_t sB = sA + OFF_B;

        #pragma unroll
        for (int ks = 0; ks < 4; ks++) {          // k16 steps in the 64-elem chunk
            uint32_t kb = (uint32_t)(ks * 32) + ksel;
            uint32_t kbA = kb ^ xorA;
            uint32_t kbB = kb ^ xorB;

            // B fragments: 4x ldsm.x4 covering n64 x k16
            uint32_t bf[8][2];
            #pragma unroll
            for (int t = 0; t < 4; t++)
                ldsm4(bf[2 * t][0], bf[2 * t + 1][0], bf[2 * t][1], bf[2 * t + 1][1],
                      sB + bRel0 + (uint32_t)(t * 16 * 128) + kbB);

            // A fragments: 2x ldsm.x4 covering m32 x k16
            uint32_t af[2][4];
            #pragma unroll
            for (int mt = 0; mt < 2; mt++)
                ldsm4(af[mt][0], af[mt][1], af[mt][2], af[mt][3],
                      sA + aRel0 + (uint32_t)(mt * 16 * 128) + kbA);

            #pragma unroll
            for (int mt = 0; mt < 2; mt++)
                #pragma unroll
                for (int nt = 0; nt < 8; nt++)
                    mma_f16(acc[mt][nt], af[mt], bf[nt]);
        }

        __syncthreads();
        int pc = i + STAGES;
        if (tid == 0 && pc < KCHUNKS) {
            uint32_t fb = sb + 8 * s;
            MBARRIER_EXPECT_TX(fb, (uint32_t)STAGE_BYTES);
            uint32_t st = sb + SMEM_DATA + s * STAGE_BYTES;
            tma2d(st,         &tmA, pc * BK, rowBase, fb);
            tma2d(st + OFF_B, &tmB, pc * BK, colBase, fb);
        }
    }

    // Epilogue: out = acc * scale[col] + bias[col]
    int row0 = rowBase + warp_m * 32 + (lane >> 2);
    int col0 = colBase + warp_n * 64 + (lane & 3) * 2;
    #pragma unroll
    for (int nt = 0; nt < 8; nt++) {
        int c = col0 + nt * 8;
        float s0 = __ldg(scales + c), s1 = __ldg(scales + c + 1);
        float b0 = __ldg(bias + c),   b1 = __ldg(bias + c + 1);
        #pragma unroll
        for (int mt = 0; mt < 2; mt++) {
            int rr = row0 + mt * 16;
            float2 v0 = make_float2(fmaf(acc[mt][nt][0], s0, b0),
                                    fmaf(acc[mt][nt][1], s1, b1));
            float2 v1 = make_float2(fmaf(acc[mt][nt][2], s0, b0),
                                    fmaf(acc[mt][nt][3], s1, b1));
            *reinterpret_cast<float2*>(out + (size_t)rr * ODIM + c) = v0;
            *reinterpret_cast<float2*>(out + (size_t)(rr + 8) * ODIM + c) = v1;
        }
    }
}

// ============================================================================
// Host side
// ============================================================================
typedef CUresult (*PFN_encodeTiled)(
    CUtensorMap*, CUtensorMapDataType, cuuint32_t, void*,
    const cuuint64_t*, const cuuint64_t*, const cuuint32_t*, const cuuint32_t*,
    CUtensorMapInterleave, CUtensorMapSwizzle, CUtensorMapL2promotion, CUtensorMapFloatOOBfill);

static PFN_encodeTiled get_encoder() {
    void* fn = nullptr;
    cudaDriverEntryPointQueryResult qr;
    cudaGetDriverEntryPointByVersion("cuTensorMapEncodeTiled", &fn, 12000,
                                     cudaEnableDefault, &qr);
    return (PFN_encodeTiled)fn;
}

static void encode_f16_2d(PFN_encodeTiled enc, CUtensorMap* tm, void* base,
                          uint64_t d0, uint64_t d1, uint32_t b0, uint32_t b1) {
    cuuint64_t gd[2] = {d0, d1};
    cuuint64_t gs[1] = {d0 * 2};   // row stride, bytes
    cuuint32_t box[2] = {b0, b1};
    cuuint32_t es[2] = {1, 1};
    enc(tm, CU_TENSOR_MAP_DATA_TYPE_FLOAT16, 2, base, gd, gs, box, es,
        CU_TENSOR_MAP_INTERLEAVE_NONE, CU_TENSOR_MAP_SWIZZLE_128B,
        CU_TENSOR_MAP_L2_PROMOTION_L2_128B, CU_TENSOR_MAP_FLOAT_OOB_FILL_NONE);
}

extern "C" void kernel_launch(void* const* d_in, const int* in_sizes, int n_in,
                              void* d_out, int out_size) {
    const float* x  = (const float*)d_in[0];
    const int*   wp = (const int*)d_in[1];
    const float* ws = (const float*)d_in[2];
    const float* bs = (const float*)d_in[3];
    float* out = (float*)d_out;

    void *pXh, *pWq;
    cudaGetSymbolAddress(&pXh, g_Xh);
    cudaGetSymbolAddress(&pWq, g_Wq);

    // 1) precompute: X -> fp16, unpack W to centered fp16
    {
        int n4 = NDIM * KDIM / 4;
        k_cvt_x<<<(n4 + 255) / 256, 256>>>((const float4*)x, (uint2*)pXh, n4);
    }
    {
        int n4 = (ODIM * (KDIM / 2)) / 4;
        k_cvt_w<<<(n4 + 255) / 256, 256>>>((const int4*)wp, (uint4*)pWq, n4);
    }

    // 2) TMA descriptors
    PFN_encodeTiled enc = get_encoder();
    CUtensorMap tA, tB;
    encode_f16_2d(enc, &tA, pXh, KDIM, NDIM, BK, BM);
    encode_f16_2d(enc, &tB, pWq, KDIM, ODIM, BK, BN);

    // 3) GEMM
    cudaFuncSetAttribute(gemm_kernel, cudaFuncAttributeMaxDynamicSharedMemorySize, SMEM_TOTAL);
    int grid = (NDIM / BM) * (ODIM / BN);   // 1024
    gemm_kernel<<<grid, 256, SMEM_TOTAL>>>(tA, tB, ws, bs, out);
}